// round 2
// baseline (speedup 1.0000x reference)
#include <cuda_runtime.h>
#include <cuda_bf16.h>
#include <cstddef>

// ---------------------------------------------------------------------------
// Shapes (all static for this problem)
// B=8 TIN=1040 IN=80 TRI=128 D=512 FFN=2048 L=8 OUT=1024
// H=8 DH=64 STRIDE=4 SEG=16 RC=4 LC=32 MAXMEM=4
// Tr=260 U=256 nseg=16 Rt=64 Q=336 K=335
// ---------------------------------------------------------------------------

#define NB 8
#define DMODEL 512
#define QROWS 336
#define KROWS 335
#define STROWS 320      // Rt + U
#define TRROWS 260
#define NSEG 16
#define NMEMS 15
#define FFND 2048
#define OUTD 1024

// device scratch buffers (allocation-free rule: __device__ globals)
__device__ float g_x[TRROWS * NB * DMODEL];
__device__ float g_state[STROWS * NB * DMODEL];
__device__ float g_state2[STROWS * NB * DMODEL];
__device__ float g_qin[QROWS * NB * DMODEL];
__device__ float g_kin[KROWS * NB * DMODEL];
__device__ float g_q[QROWS * NB * DMODEL];
__device__ float g_k[KROWS * NB * DMODEL];
__device__ float g_v[KROWS * NB * DMODEL];
__device__ float g_att[QROWS * NB * DMODEL];
__device__ float g_out[QROWS * NB * DMODEL];
__device__ float g_mems[NMEMS * NB * DMODEL];
__device__ float g_h1[STROWS * NB * DMODEL];
__device__ float g_f1[STROWS * NB * FFND];
__device__ float g_f2[STROWS * NB * DMODEL];
__device__ float g_yin[2048 * DMODEL];
__device__ float g_yt[2048 * OUTD];

// ---------------------------------------------------------------------------
// Input projection + fold: input(8,1040,80)@w_in(80,128) -> x(260,8,512)
// x[tt, b, (t&3)*128 + j] = sum_k input[b, tt*4 + (t&3), k] * w_in[k, j]
// ---------------------------------------------------------------------------
__global__ void inproj_kernel(const float* __restrict__ inp,
                              const float* __restrict__ w,
                              float* __restrict__ xout) {
    int t = blockIdx.x;   // 0..1039
    int b = blockIdx.y;   // 0..7
    __shared__ float sh[80];
    int tid = threadIdx.x; // 128
    if (tid < 80) sh[tid] = inp[((size_t)b * 1040 + t) * 80 + tid];
    __syncthreads();
    float s = 0.f;
#pragma unroll 16
    for (int k = 0; k < 80; k++) s += sh[k] * w[k * 128 + tid];
    xout[(((size_t)(t >> 2)) * NB + b) * DMODEL + (t & 3) * 128 + tid] = s;
}

// state rows 0..63 = rc (gathered), rows 64..319 = utt (x rows 0..255)
__global__ void state_init_kernel(const float* __restrict__ x, float* __restrict__ st) {
    int i = blockIdx.x * blockDim.x + threadIdx.x;
    if (i >= STROWS * NB * DMODEL) return;
    int d = i & 511;
    int b = (i >> 9) & 7;
    int r = i >> 12;
    int src = (r < 64) ? (((r >> 2) + 1) * 16 + (r & 3)) : (r - 64);
    st[i] = x[((size_t)src * NB + b) * DMODEL + d];
}

// mems0[s,b,d] = mean over 16 of x[s*16+t, b, d], s<15
__global__ void mems0_kernel(const float* __restrict__ x, float* __restrict__ mems) {
    int i = blockIdx.x * blockDim.x + threadIdx.x;
    if (i >= NMEMS * NB * DMODEL) return;
    int d = i & 511;
    int b = (i >> 9) & 7;
    int s = i >> 12;
    float acc = 0.f;
    size_t base = ((size_t)(s * 16) * NB + b) * DMODEL + d;
    for (int t = 0; t < 16; t++) acc += x[base + (size_t)t * NB * DMODEL];
    mems[i] = acc * (1.0f / 16.0f);
}

// summary rows (written into qin rows 320..335): mean of ln_utt per segment
__global__ void summary_kernel(const float* __restrict__ qin, float* __restrict__ dst) {
    int i = blockIdx.x * blockDim.x + threadIdx.x;
    if (i >= NSEG * NB * DMODEL) return;
    int d = i & 511;
    int b = (i >> 9) & 7;
    int s = i >> 12;
    float acc = 0.f;
    size_t base = ((size_t)(64 + s * 16) * NB + b) * DMODEL + d;
    for (int t = 0; t < 16; t++) acc += qin[base + (size_t)t * NB * DMODEL];
    dst[i] = acc * (1.0f / 16.0f);
}

// mems <- tanh(out rows 320..334)
__global__ void mems_tanh_kernel(const float* __restrict__ out, float* __restrict__ mems) {
    int i = blockIdx.x * blockDim.x + threadIdx.x;
    if (i >= NMEMS * NB * DMODEL) return;
    mems[i] = tanhf(out[(size_t)STROWS * NB * DMODEL + i]);
}

// yin[(b*256+t)*512+d] = state[(64+t)*8+b, d]
__global__ void ytrans_kernel(const float* __restrict__ st, float* __restrict__ yin) {
    int i = blockIdx.x * blockDim.x + threadIdx.x;
    if (i >= 2048 * DMODEL) return;
    int d = i & 511;
    int m = i >> 9;
    int b = m >> 8;
    int t = m & 255;
    yin[i] = st[((size_t)(64 + t) * NB + b) * DMODEL + d];
}

__global__ void lr_kernel(const int* __restrict__ lengths, float* __restrict__ out) {
    int b = threadIdx.x;
    if (b < 8) out[8u * 256u * 1024u + b] = (float)(lengths[b] >> 2);
}

// ---------------------------------------------------------------------------
// LayerNorm (two-pass), optional residual add + optional pre-LN sum output.
// One block per row, 128 threads. N <= 1024.
// ---------------------------------------------------------------------------
__global__ void ln_kernel(const float* __restrict__ in, const float* __restrict__ addin,
                          float* __restrict__ outsum, float* __restrict__ outln,
                          const float* __restrict__ g, const float* __restrict__ bta,
                          int N) {
    __shared__ float sh[1024];
    __shared__ float red[4];
    __shared__ float stat[2];
    int row = blockIdx.x, tid = threadIdx.x;
    size_t base = (size_t)row * N;
    float s = 0.f;
    for (int c = tid; c < N; c += 128) {
        float v = in[base + c];
        if (addin) v += addin[base + c];
        sh[c] = v;
        s += v;
    }
    for (int o = 16; o; o >>= 1) s += __shfl_xor_sync(0xffffffffu, s, o);
    if ((tid & 31) == 0) red[tid >> 5] = s;
    __syncthreads();
    if (tid == 0) stat[0] = (red[0] + red[1] + red[2] + red[3]) / (float)N;
    __syncthreads();
    float mean = stat[0];
    float vs = 0.f;
    for (int c = tid; c < N; c += 128) {
        float d = sh[c] - mean;
        vs += d * d;
    }
    for (int o = 16; o; o >>= 1) vs += __shfl_xor_sync(0xffffffffu, vs, o);
    if ((tid & 31) == 0) red[tid >> 5] = vs;
    __syncthreads();
    if (tid == 0) stat[1] = rsqrtf((red[0] + red[1] + red[2] + red[3]) / (float)N + 1e-5f);
    __syncthreads();
    float rstd = stat[1];
    for (int c = tid; c < N; c += 128) {
        float v = sh[c];
        if (outsum) outsum[base + c] = v;
        outln[base + c] = (v - mean) * rstd * g[c] + bta[c];
    }
}

// ---------------------------------------------------------------------------
// SGEMM: C[M,N] = A[M,K] @ B[K,N] + bias[N], optional relu.
// BM=128 BN=64 BK=16, 256 threads, per-thread 8x4.
// K % 16 == 0, N % 64 == 0; M arbitrary (guarded).
// ---------------------------------------------------------------------------
__global__ __launch_bounds__(256) void sgemm(const float* __restrict__ A,
                                             const float* __restrict__ B,
                                             const float* __restrict__ bias,
                                             float* __restrict__ C,
                                             int M, int N, int K, int act) {
    __shared__ float As[16][128];
    __shared__ float Bs[16][64];
    int tid = threadIdx.x;
    int row0 = blockIdx.y * 128;
    int col0 = blockIdx.x * 64;
    int ty = tid >> 4, tx = tid & 15;
    float acc[8][4];
#pragma unroll
    for (int i = 0; i < 8; i++)
#pragma unroll
        for (int j = 0; j < 4; j++) acc[i][j] = 0.f;

    for (int k0 = 0; k0 < K; k0 += 16) {
#pragma unroll
        for (int i = 0; i < 2; i++) {
            int id = tid * 2 + i;
            int ar = id >> 2;
            int kq = (id & 3) * 4;
            float4 v = make_float4(0.f, 0.f, 0.f, 0.f);
            int gr = row0 + ar;
            if (gr < M) v = *(const float4*)&A[(size_t)gr * K + k0 + kq];
            As[kq + 0][ar] = v.x;
            As[kq + 1][ar] = v.y;
            As[kq + 2][ar] = v.z;
            As[kq + 3][ar] = v.w;
        }
        {
            int kk = tid >> 4;
            int nq = (tid & 15) * 4;
            float4 v = *(const float4*)&B[(size_t)(k0 + kk) * N + col0 + nq];
            *(float4*)&Bs[kk][nq] = v;
        }
        __syncthreads();
#pragma unroll
        for (int kk = 0; kk < 16; kk++) {
            float a[8], bb[4];
            *(float4*)&a[0] = *(const float4*)&As[kk][ty * 8];
            *(float4*)&a[4] = *(const float4*)&As[kk][ty * 8 + 4];
            *(float4*)&bb[0] = *(const float4*)&Bs[kk][tx * 4];
#pragma unroll
            for (int i = 0; i < 8; i++)
#pragma unroll
                for (int j = 0; j < 4; j++) acc[i][j] += a[i] * bb[j];
        }
        __syncthreads();
    }
#pragma unroll
    for (int i = 0; i < 8; i++) {
        int gr = row0 + ty * 8 + i;
        if (gr >= M) break;
#pragma unroll
        for (int j = 0; j < 4; j++) {
            float v = acc[i][j] + bias[col0 + tx * 4 + j];
            if (act) v = fmaxf(v, 0.f);
            C[(size_t)gr * N + col0 + tx * 4 + j] = v;
        }
    }
}

// ---------------------------------------------------------------------------
// Attention mask (static structure): query row -> segment, key col regions:
// [0,15) mems, [15,79) rc, [79,335) utt
// ---------------------------------------------------------------------------
__device__ __forceinline__ bool attn_allowed(int qrow, int kc) {
    int i, typ;
    if (qrow < 64) { i = qrow >> 2; typ = 0; }
    else if (qrow < 320) { i = (qrow - 64) >> 4; typ = 1; }
    else { i = qrow - 320; typ = 2; }
    if (kc < 15) {
        if (typ == 2) return false;
        int ms = i - 4; if (ms < 0) ms = 0;
        return (kc >= ms) && (kc < i);
    } else if (kc < 79) {
        int c = kc - 15;
        return (c >> 2) == i;
    } else {
        int c = kc - 79;
        int ss = i * 16 - 32; if (ss < 0) ss = 0;
        int se = i * 16 + 16; if (se > 256) se = 256;
        return (c >= ss) && (c < se);
    }
}

// Fused attention: block = (qtile of 16 rows, head h, batch b), 128 threads.
__global__ __launch_bounds__(128) void attn_kernel(const float* __restrict__ Qb,
                                                   const float* __restrict__ Kb,
                                                   const float* __restrict__ Vb,
                                                   const int* __restrict__ lengths,
                                                   float* __restrict__ Ob) {
    __shared__ float qs[16][64];
    __shared__ float sc[16][336];
    __shared__ float ch[32][65];   // +1 pad: kill bank conflicts on ch[kk][d]
    __shared__ float rowsum[16];
    int b = blockIdx.z, h = blockIdx.y, qt = blockIdx.x;
    int tid = threadIdx.x;

    int lrb = lengths[b] >> 2;
    int maxlr = 0;
#pragma unroll
    for (int i = 0; i < 8; i++) {
        int v = lengths[i] >> 2;
        maxlr = max(maxlr, v);
    }
    int klen = 335 - (maxlr - lrb);

    for (int i = tid; i < 16 * 64; i += 128) {
        int r = i >> 6, d = i & 63;
        qs[r][d] = Qb[(((size_t)(qt * 16 + r)) * NB + b) * DMODEL + h * 64 + d] * 0.125f;
    }
    __syncthreads();

    int r = tid >> 3;
    int cg = (tid & 7) * 4;
    int qrow = qt * 16 + r;

    // ---- scores ----
    for (int kc0 = 0; kc0 < KROWS; kc0 += 32) {
        int kcnt = min(32, KROWS - kc0);
        for (int i = tid; i < kcnt * 64; i += 128) {
            int kk = i >> 6, d = i & 63;
            ch[kk][d] = Kb[(((size_t)(kc0 + kk)) * NB + b) * DMODEL + h * 64 + d];
        }
        __syncthreads();
        float a0 = 0.f, a1 = 0.f, a2 = 0.f, a3 = 0.f;
#pragma unroll
        for (int d = 0; d < 64; d++) {
            float qv = qs[r][d];
            a0 += qv * ch[cg + 0][d];
            a1 += qv * ch[cg + 1][d];
            a2 += qv * ch[cg + 2][d];
            a3 += qv * ch[cg + 3][d];
        }
        float av[4] = {a0, a1, a2, a3};
#pragma unroll
        for (int j = 0; j < 4; j++) {
            int kc = kc0 + cg + j;
            if (kc < KROWS) {
                sc[r][kc] = (kc < klen && attn_allowed(qrow, kc)) ? av[j] : -1e8f;
            }
        }
        __syncthreads();
    }

    // ---- softmax (8 lanes per row) ----
    {
        int j = tid & 7;
        float m = -3.0e38f;
        for (int c = j; c < KROWS; c += 8) m = fmaxf(m, sc[r][c]);
        for (int o = 4; o; o >>= 1) m = fmaxf(m, __shfl_xor_sync(0xffffffffu, m, o));
        float s = 0.f;
        for (int c = j; c < KROWS; c += 8) {
            float e = __expf(sc[r][c] - m);
            sc[r][c] = e;
            s += e;
        }
        for (int o = 4; o; o >>= 1) s += __shfl_xor_sync(0xffffffffu, s, o);
        if (j == 0) rowsum[r] = s;
    }
    __syncthreads();

    // ---- probs @ V ----
    int dg = (tid & 7) * 8;
    float acc[8] = {0, 0, 0, 0, 0, 0, 0, 0};
    for (int kc0 = 0; kc0 < KROWS; kc0 += 32) {
        int kcnt = min(32, KROWS - kc0);
        for (int i = tid; i < kcnt * 64; i += 128) {
            int kk = i >> 6, d = i & 63;
            ch[kk][d] = Vb[(((size_t)(kc0 + kk)) * NB + b) * DMODEL + h * 64 + d];
        }
        __syncthreads();
        for (int kk = 0; kk < kcnt; kk++) {
            float p = sc[r][kc0 + kk];
#pragma unroll
            for (int u = 0; u < 8; u++) acc[u] += p * ch[kk][dg + u];
        }
        __syncthreads();
    }
    float inv = 1.0f / rowsum[r];
#pragma unroll
    for (int u = 0; u < 8; u++)
        Ob[(((size_t)qrow) * NB + b) * DMODEL + h * 64 + dg + u] = acc[u] * inv;
}

// ---------------------------------------------------------------------------
// Host driver
// ---------------------------------------------------------------------------
extern "C" void kernel_launch(void* const* d_in, const int* in_sizes, int n_in,
                              void* d_out, int out_size) {
    const float* input   = (const float*)d_in[0];
    const int*   lengths = (const int*)d_in[1];
    const float* w_in    = (const float*)d_in[2];
    const float* ln_in_g = (const float*)d_in[3];
    const float* ln_in_b = (const float*)d_in[4];
    const float* wq      = (const float*)d_in[5];
    const float* bq      = (const float*)d_in[6];
    const float* wk      = (const float*)d_in[7];
    const float* bk      = (const float*)d_in[8];
    const float* wv      = (const float*)d_in[9];
    const float* bv      = (const float*)d_in[10];
    const float* wo      = (const float*)d_in[11];
    const float* bo      = (const float*)d_in[12];
    const float* ff_ln_g = (const float*)d_in[13];
    const float* ff_ln_b = (const float*)d_in[14];
    const float* w1      = (const float*)d_in[15];
    const float* b1      = (const float*)d_in[16];
    const float* w2      = (const float*)d_in[17];
    const float* b2      = (const float*)d_in[18];
    const float* ln_out_g = (const float*)d_in[19];
    const float* ln_out_b = (const float*)d_in[20];
    const float* w_out   = (const float*)d_in[21];
    const float* b_out   = (const float*)d_in[22];
    const float* lng     = (const float*)d_in[23];
    const float* lnb     = (const float*)d_in[24];
    float* out = (float*)d_out;

    float *px, *pstate, *pstate2, *pqin, *pkin, *pq, *pk, *pv, *patt, *pout2;
    float *pmems, *ph1, *pf1, *pf2, *pyin, *pyt;
    cudaGetSymbolAddress((void**)&px, g_x);
    cudaGetSymbolAddress((void**)&pstate, g_state);
    cudaGetSymbolAddress((void**)&pstate2, g_state2);
    cudaGetSymbolAddress((void**)&pqin, g_qin);
    cudaGetSymbolAddress((void**)&pkin, g_kin);
    cudaGetSymbolAddress((void**)&pq, g_q);
    cudaGetSymbolAddress((void**)&pk, g_k);
    cudaGetSymbolAddress((void**)&pv, g_v);
    cudaGetSymbolAddress((void**)&patt, g_att);
    cudaGetSymbolAddress((void**)&pout2, g_out);
    cudaGetSymbolAddress((void**)&pmems, g_mems);
    cudaGetSymbolAddress((void**)&ph1, g_h1);
    cudaGetSymbolAddress((void**)&pf1, g_f1);
    cudaGetSymbolAddress((void**)&pf2, g_f2);
    cudaGetSymbolAddress((void**)&pyin, g_yin);
    cudaGetSymbolAddress((void**)&pyt, g_yt);

    // input proj + reshape/transpose
    inproj_kernel<<<dim3(1040, 8), 128>>>(input, w_in, px);
    state_init_kernel<<<(STROWS * NB * DMODEL + 255) / 256, 256>>>(px, pstate);
    mems0_kernel<<<(NMEMS * NB * DMODEL + 255) / 256, 256>>>(px, pmems);

    const size_t WSTRIDE = (size_t)DMODEL * DMODEL;

    for (int l = 0; l < 8; l++) {
        // LN1 -> qin rows 0..319
        ln_kernel<<<STROWS * NB, 128>>>(pstate, nullptr, nullptr, pqin,
                                        ln_in_g + l * DMODEL, ln_in_b + l * DMODEL, DMODEL);
        // summary -> qin rows 320..335
        summary_kernel<<<(NSEG * NB * DMODEL + 255) / 256, 256>>>(
            pqin, pqin + (size_t)STROWS * NB * DMODEL);
        // kin = [mems, ln_rc, ln_utt]
        cudaMemcpyAsync(pkin, pmems, (size_t)NMEMS * NB * DMODEL * sizeof(float),
                        cudaMemcpyDeviceToDevice);
        cudaMemcpyAsync(pkin + (size_t)NMEMS * NB * DMODEL, pqin,
                        (size_t)STROWS * NB * DMODEL * sizeof(float),
                        cudaMemcpyDeviceToDevice);
        // projections
        sgemm<<<dim3(8, 21), 256>>>(pqin, wq + l * WSTRIDE, bq + l * DMODEL, pq,
                                    QROWS * NB, DMODEL, DMODEL, 0);
        sgemm<<<dim3(8, 21), 256>>>(pkin, wk + l * WSTRIDE, bk + l * DMODEL, pk,
                                    KROWS * NB, DMODEL, DMODEL, 0);
        sgemm<<<dim3(8, 21), 256>>>(pkin, wv + l * WSTRIDE, bv + l * DMODEL, pv,
                                    KROWS * NB, DMODEL, DMODEL, 0);
        // attention
        attn_kernel<<<dim3(21, 8, 8), 128>>>(pq, pk, pv, lengths, patt);
        // output projection
        sgemm<<<dim3(8, 21), 256>>>(patt, wo + l * WSTRIDE, bo + l * DMODEL, pout2,
                                    QROWS * NB, DMODEL, DMODEL, 0);
        // new mems = tanh(out rows 320..334)
        mems_tanh_kernel<<<(NMEMS * NB * DMODEL + 255) / 256, 256>>>(pout2, pmems);
        // res = out[:320] + state; state2 = res; h1 = LN(res)
        ln_kernel<<<STROWS * NB, 128>>>(pout2, pstate, pstate2, ph1,
                                        ff_ln_g + l * DMODEL, ff_ln_b + l * DMODEL, DMODEL);
        // FFN
        sgemm<<<dim3(32, 20), 256>>>(ph1, w1 + (size_t)l * DMODEL * FFND, b1 + l * FFND,
                                     pf1, STROWS * NB, FFND, DMODEL, 1);
        sgemm<<<dim3(8, 20), 256>>>(pf1, w2 + (size_t)l * FFND * DMODEL, b2 + l * DMODEL,
                                    pf2, STROWS * NB, DMODEL, FFND, 0);
        // state = LN(state2 + f2)
        ln_kernel<<<STROWS * NB, 128>>>(pf2, pstate2, nullptr, pstate,
                                        ln_out_g + l * DMODEL, ln_out_b + l * DMODEL, DMODEL);
    }

    // final: y = LN(transpose(utt) @ w_out + b_out)
    ytrans_kernel<<<(2048 * DMODEL + 255) / 256, 256>>>(pstate, pyin);
    sgemm<<<dim3(16, 16), 256>>>(pyin, w_out, b_out, pyt, 2048, OUTD, DMODEL, 0);
    ln_kernel<<<2048, 128>>>(pyt, nullptr, nullptr, out, lng, lnb, OUTD);

    // lr = lengths // 4, appended after y if the output buffer includes it
    if (out_size >= 8 * 256 * 1024 + 8) {
        lr_kernel<<<1, 8>>>(lengths, out);
    }
}

// round 5
// speedup vs baseline: 1.1681x; 1.1681x over previous
#include <cuda_runtime.h>
#include <cuda_bf16.h>
#include <cstddef>

// ---------------------------------------------------------------------------
// Shapes (all static): B=8 TIN=1040 IN=80 TRI=128 D=512 FFN=2048 L=8 OUT=1024
// H=8 DH=64 STRIDE=4 SEG=16 RC=4 LC=32 MAXMEM=4
// Tr=260 U=256 nseg=16 Rt=64 Q=336 K=335
// ---------------------------------------------------------------------------

#define NB 8
#define DMODEL 512
#define QROWS 336
#define KROWS 335
#define STROWS 320
#define TRROWS 260
#define NSEG 16
#define NMEMS 15
#define FFND 2048
#define OUTD 1024

// packed fp32x2 (Blackwell FFMA2 — ptxas never emits this from C++)
#define FMA2(d, a, b) asm("fma.rn.f32x2 %0, %1, %2, %0;" : "+l"(d) : "l"(a), "l"(b))
#define PACK2(d, x)   asm("mov.b64 %0, {%1, %1};" : "=l"(d) : "f"(x))

// device scratch (allocation-free rule: __device__ globals)
__device__ float g_x[TRROWS * NB * DMODEL];
__device__ float g_state[STROWS * NB * DMODEL];
__device__ float g_state2[STROWS * NB * DMODEL];
__device__ float g_qin[QROWS * NB * DMODEL];
__device__ float g_kin[KROWS * NB * DMODEL];
__device__ float g_q[QROWS * NB * DMODEL];
__device__ float g_k[KROWS * NB * DMODEL];
__device__ float g_v[KROWS * NB * DMODEL];
__device__ float g_att[QROWS * NB * DMODEL];
__device__ float g_out[QROWS * NB * DMODEL];
__device__ float g_h1[STROWS * NB * DMODEL];
__device__ float g_f1[STROWS * NB * FFND];
__device__ float g_f2[STROWS * NB * DMODEL];
__device__ float g_yin[2048 * DMODEL];
__device__ float g_yt[2048 * OUTD];

// ---------------------------------------------------------------------------
// small utility kernels
// ---------------------------------------------------------------------------
__global__ void inproj_kernel(const float* __restrict__ inp,
                              const float* __restrict__ w,
                              float* __restrict__ xout) {
    int t = blockIdx.x, b = blockIdx.y;
    __shared__ float sh[80];
    int tid = threadIdx.x;
    if (tid < 80) sh[tid] = inp[((size_t)b * 1040 + t) * 80 + tid];
    __syncthreads();
    float s = 0.f;
#pragma unroll 16
    for (int k = 0; k < 80; k++) s += sh[k] * w[k * 128 + tid];
    xout[(((size_t)(t >> 2)) * NB + b) * DMODEL + (t & 3) * 128 + tid] = s;
}

__global__ void state_init_kernel(const float* __restrict__ x, float* __restrict__ st) {
    int i = blockIdx.x * blockDim.x + threadIdx.x;
    if (i >= STROWS * NB * DMODEL) return;
    int d = i & 511;
    int b = (i >> 9) & 7;
    int r = i >> 12;
    int src = (r < 64) ? (((r >> 2) + 1) * 16 + (r & 3)) : (r - 64);
    st[i] = x[((size_t)src * NB + b) * DMODEL + d];
}

// writes initial mems directly into kin rows [0,15)
__global__ void mems0_kernel(const float* __restrict__ x, float* __restrict__ kin) {
    int i = blockIdx.x * blockDim.x + threadIdx.x;
    if (i >= NMEMS * NB * DMODEL) return;
    int d = i & 511;
    int b = (i >> 9) & 7;
    int s = i >> 12;
    float acc = 0.f;
    size_t base = ((size_t)(s * 16) * NB + b) * DMODEL + d;
    for (int t = 0; t < 16; t++) acc += x[base + (size_t)t * NB * DMODEL];
    kin[i] = acc * (1.0f / 16.0f);
}

__global__ void summary_kernel(const float* __restrict__ qin, float* __restrict__ dst) {
    int i = blockIdx.x * blockDim.x + threadIdx.x;
    if (i >= NSEG * NB * DMODEL) return;
    int d = i & 511;
    int b = (i >> 9) & 7;
    int s = i >> 12;
    float acc = 0.f;
    size_t base = ((size_t)(64 + s * 16) * NB + b) * DMODEL + d;
    for (int t = 0; t < 16; t++) acc += qin[base + (size_t)t * NB * DMODEL];
    dst[i] = acc * (1.0f / 16.0f);
}

// new mems = tanh(out rows 320..334) written directly into kin rows [0,15)
__global__ void mems_tanh_kernel(const float* __restrict__ out, float* __restrict__ kin) {
    int i = blockIdx.x * blockDim.x + threadIdx.x;
    if (i >= NMEMS * NB * DMODEL) return;
    kin[i] = tanhf(out[(size_t)STROWS * NB * DMODEL + i]);
}

__global__ void ytrans_kernel(const float* __restrict__ st, float* __restrict__ yin) {
    int i = blockIdx.x * blockDim.x + threadIdx.x;
    if (i >= 2048 * DMODEL) return;
    int d = i & 511;
    int m = i >> 9;
    int b = m >> 8;
    int t = m & 255;
    yin[i] = st[((size_t)(64 + t) * NB + b) * DMODEL + d];
}

__global__ void lr_kernel(const int* __restrict__ lengths, float* __restrict__ out) {
    int b = threadIdx.x;
    if (b < 8) out[8u * 256u * 1024u + b] = (float)(lengths[b] >> 2);
}

// ---------------------------------------------------------------------------
// Vectorized LayerNorm. One block per row, 128 threads, row in registers.
// N = 512 or 1024. Optional residual input, pre-LN sum output, 2nd LN dest.
// ---------------------------------------------------------------------------
template <int N>
__global__ __launch_bounds__(128) void ln4_kernel(const float* __restrict__ in,
                                                  const float* __restrict__ addin,
                                                  float* __restrict__ outsum,
                                                  float* __restrict__ outln,
                                                  float* __restrict__ outln2,
                                                  const float* __restrict__ g,
                                                  const float* __restrict__ be) {
    constexpr int NV = N / 512;
    __shared__ float red[4];
    __shared__ float stat[2];
    int row = blockIdx.x, tid = threadIdx.x;
    size_t base = (size_t)row * N;
    float4 v[NV];
    float s = 0.f;
#pragma unroll
    for (int i = 0; i < NV; i++) {
        int c = (i * 128 + tid) * 4;
        float4 a = *(const float4*)&in[base + c];
        if (addin) {
            float4 r2 = *(const float4*)&addin[base + c];
            a.x += r2.x; a.y += r2.y; a.z += r2.z; a.w += r2.w;
        }
        v[i] = a;
        s += a.x + a.y + a.z + a.w;
    }
    for (int o = 16; o; o >>= 1) s += __shfl_xor_sync(0xffffffffu, s, o);
    if ((tid & 31) == 0) red[tid >> 5] = s;
    __syncthreads();
    if (tid == 0) stat[0] = (red[0] + red[1] + red[2] + red[3]) * (1.0f / N);
    __syncthreads();
    float mean = stat[0];
    float vs = 0.f;
#pragma unroll
    for (int i = 0; i < NV; i++) {
        float dx = v[i].x - mean, dy = v[i].y - mean, dz = v[i].z - mean, dw = v[i].w - mean;
        vs += dx * dx + dy * dy + dz * dz + dw * dw;
    }
    for (int o = 16; o; o >>= 1) vs += __shfl_xor_sync(0xffffffffu, vs, o);
    if ((tid & 31) == 0) red[tid >> 5] = vs;
    __syncthreads();
    if (tid == 0) stat[1] = rsqrtf((red[0] + red[1] + red[2] + red[3]) * (1.0f / N) + 1e-5f);
    __syncthreads();
    float rstd = stat[1];
#pragma unroll
    for (int i = 0; i < NV; i++) {
        int c = (i * 128 + tid) * 4;
        if (outsum) *(float4*)&outsum[base + c] = v[i];
        float4 gv = *(const float4*)&g[c];
        float4 bv = *(const float4*)&be[c];
        float4 o;
        o.x = (v[i].x - mean) * rstd * gv.x + bv.x;
        o.y = (v[i].y - mean) * rstd * gv.y + bv.y;
        o.z = (v[i].z - mean) * rstd * gv.z + bv.z;
        o.w = (v[i].w - mean) * rstd * gv.w + bv.w;
        *(float4*)&outln[base + c] = o;
        if (outln2) *(float4*)&outln2[base + c] = o;
    }
}

// ---------------------------------------------------------------------------
// SGEMM v2: BM=128 BN=64 BK=16, 256 threads, per-thread 8x4 via f32x2 pairs
// over rows. Double-buffered shared tiles with register prefetch.
// ---------------------------------------------------------------------------
__device__ __forceinline__ void sgemm_body(const float* __restrict__ A,
                                           const float* __restrict__ B,
                                           const float* __restrict__ bias,
                                           float* __restrict__ C,
                                           int M, int N, int K, int act,
                                           float* sA, float* sB) {
    int tid = threadIdx.x;
    int row0 = blockIdx.y * 128;
    int col0 = blockIdx.x * 64;
    int ty = tid >> 4, tx = tid & 15;

    // A loader: each thread loads one row (ar), 8 consecutive k values
    int ar = tid >> 1;
    int kq = (tid & 1) * 8;
    // B loader
    int bkk = tid >> 4;
    int bnq = (tid & 15) * 4;

    unsigned long long acc[4][4];
#pragma unroll
    for (int i = 0; i < 4; i++)
#pragma unroll
        for (int j = 0; j < 4; j++) acc[i][j] = 0ull;

    int gr = row0 + ar;
    bool arow_ok = (gr < M);
    const float* Arow = A + (size_t)(arow_ok ? gr : 0) * K;

    float4 pa0, pa1, pb;
    // preload tile 0
    pa0 = arow_ok ? *(const float4*)&Arow[kq] : make_float4(0, 0, 0, 0);
    pa1 = arow_ok ? *(const float4*)&Arow[kq + 4] : make_float4(0, 0, 0, 0);
    pb = *(const float4*)&B[(size_t)bkk * N + col0 + bnq];

    sA[(kq + 0) * 128 + ar] = pa0.x;
    sA[(kq + 1) * 128 + ar] = pa0.y;
    sA[(kq + 2) * 128 + ar] = pa0.z;
    sA[(kq + 3) * 128 + ar] = pa0.w;
    sA[(kq + 4) * 128 + ar] = pa1.x;
    sA[(kq + 5) * 128 + ar] = pa1.y;
    sA[(kq + 6) * 128 + ar] = pa1.z;
    sA[(kq + 7) * 128 + ar] = pa1.w;
    *(float4*)&sB[bkk * 64 + bnq] = pb;
    __syncthreads();

    int nk = K >> 4;
    int buf = 0;
    for (int t = 0; t < nk; t++) {
        if (t + 1 < nk) {
            int k0 = (t + 1) << 4;
            pa0 = arow_ok ? *(const float4*)&Arow[k0 + kq] : make_float4(0, 0, 0, 0);
            pa1 = arow_ok ? *(const float4*)&Arow[k0 + kq + 4] : make_float4(0, 0, 0, 0);
            pb = *(const float4*)&B[(size_t)(k0 + bkk) * N + col0 + bnq];
        }
        const float* a_ = sA + buf * 2048;
        const float* b_ = sB + buf * 1024;
#pragma unroll
        for (int kk = 0; kk < 16; kk++) {
            unsigned long long av[4];
#pragma unroll
            for (int ip = 0; ip < 4; ip++)
                av[ip] = *(const unsigned long long*)&a_[kk * 128 + ty * 8 + 2 * ip];
            float4 bv = *(const float4*)&b_[kk * 64 + tx * 4];
            unsigned long long bd[4];
            PACK2(bd[0], bv.x);
            PACK2(bd[1], bv.y);
            PACK2(bd[2], bv.z);
            PACK2(bd[3], bv.w);
#pragma unroll
            for (int ip = 0; ip < 4; ip++) {
                FMA2(acc[ip][0], av[ip], bd[0]);
                FMA2(acc[ip][1], av[ip], bd[1]);
                FMA2(acc[ip][2], av[ip], bd[2]);
                FMA2(acc[ip][3], av[ip], bd[3]);
            }
        }
        if (t + 1 < nk) {
            int nb = buf ^ 1;
            float* dA = sA + nb * 2048;
            dA[(kq + 0) * 128 + ar] = pa0.x;
            dA[(kq + 1) * 128 + ar] = pa0.y;
            dA[(kq + 2) * 128 + ar] = pa0.z;
            dA[(kq + 3) * 128 + ar] = pa0.w;
            dA[(kq + 4) * 128 + ar] = pa1.x;
            dA[(kq + 5) * 128 + ar] = pa1.y;
            dA[(kq + 6) * 128 + ar] = pa1.z;
            dA[(kq + 7) * 128 + ar] = pa1.w;
            *(float4*)&sB[nb * 1024 + bkk * 64 + bnq] = pb;
            __syncthreads();
            buf = nb;
        }
    }

    float4 bias4 = *(const float4*)&bias[col0 + tx * 4];
#pragma unroll
    for (int ip = 0; ip < 4; ip++) {
        float2 c0 = *(float2*)&acc[ip][0];
        float2 c1 = *(float2*)&acc[ip][1];
        float2 c2 = *(float2*)&acc[ip][2];
        float2 c3 = *(float2*)&acc[ip][3];
        int re = row0 + ty * 8 + 2 * ip;
        float4 o0 = make_float4(c0.x + bias4.x, c1.x + bias4.y, c2.x + bias4.z, c3.x + bias4.w);
        float4 o1 = make_float4(c0.y + bias4.x, c1.y + bias4.y, c2.y + bias4.z, c3.y + bias4.w);
        if (act) {
            o0.x = fmaxf(o0.x, 0.f); o0.y = fmaxf(o0.y, 0.f);
            o0.z = fmaxf(o0.z, 0.f); o0.w = fmaxf(o0.w, 0.f);
            o1.x = fmaxf(o1.x, 0.f); o1.y = fmaxf(o1.y, 0.f);
            o1.z = fmaxf(o1.z, 0.f); o1.w = fmaxf(o1.w, 0.f);
        }
        if (re < M)     *(float4*)&C[(size_t)re * N + col0 + tx * 4] = o0;
        if (re + 1 < M) *(float4*)&C[(size_t)(re + 1) * N + col0 + tx * 4] = o1;
    }
}

__global__ __launch_bounds__(256) void sgemm2(const float* __restrict__ A,
                                              const float* __restrict__ B,
                                              const float* __restrict__ bias,
                                              float* __restrict__ C,
                                              int M, int N, int K, int act) {
    __shared__ float sA[2 * 2048];
    __shared__ float sB[2 * 1024];
    sgemm_body(A, B, bias, C, M, N, K, act, sA, sB);
}

// fused Q/K/V projections: blockIdx.z selects which GEMM
__global__ __launch_bounds__(256) void sgemm_qkv(
    const float* __restrict__ qin, const float* __restrict__ kin,
    const float* __restrict__ wq, const float* __restrict__ wk, const float* __restrict__ wv,
    const float* __restrict__ bq, const float* __restrict__ bk, const float* __restrict__ bv,
    float* __restrict__ q, float* __restrict__ k, float* __restrict__ v) {
    __shared__ float sA[2 * 2048];
    __shared__ float sB[2 * 1024];
    int z = blockIdx.z;
    const float* A = (z == 0) ? qin : kin;
    const float* W = (z == 0) ? wq : (z == 1) ? wk : wv;
    const float* bi = (z == 0) ? bq : (z == 1) ? bk : bv;
    float* C = (z == 0) ? q : (z == 1) ? k : v;
    int M = (z == 0) ? QROWS * NB : KROWS * NB;
    sgemm_body(A, W, bi, C, M, DMODEL, DMODEL, 0, sA, sB);
}

// ---------------------------------------------------------------------------
// Attention mask (static structure)
// ---------------------------------------------------------------------------
__device__ __forceinline__ bool attn_allowed(int qrow, int kc) {
    int i, typ;
    if (qrow < 64) { i = qrow >> 2; typ = 0; }
    else if (qrow < 320) { i = (qrow - 64) >> 4; typ = 1; }
    else { i = qrow - 320; typ = 2; }
    if (kc < 15) {
        if (typ == 2) return false;
        int ms = i - 4; if (ms < 0) ms = 0;
        return (kc >= ms) && (kc < i);
    } else if (kc < 79) {
        int c = kc - 15;
        return (c >> 2) == i;
    } else {
        int c = kc - 79;
        int ss = i * 16 - 32; if (ss < 0) ss = 0;
        int se = i * 16 + 16; if (se > 256) se = 256;
        return (c >= ss) && (c < se);
    }
}

// Fused attention: block = (qtile of 16 rows, head h, batch b), 128 threads.
__global__ __launch_bounds__(128) void attn_kernel(const float* __restrict__ Qb,
                                                   const float* __restrict__ Kb,
                                                   const float* __restrict__ Vb,
                                                   const int* __restrict__ lengths,
                                                   float* __restrict__ Ob) {
    __shared__ float qs[16][66];
    __shared__ float sc[16][336];
    __shared__ float ch[32][66];
    __shared__ float rowsum[16];
    int b = blockIdx.z, h = blockIdx.y, qt = blockIdx.x;
    int tid = threadIdx.x;

    int lrb = lengths[b] >> 2;
    int maxlr = 0;
#pragma unroll
    for (int i = 0; i < 8; i++) {
        int v = lengths[i] >> 2;
        maxlr = max(maxlr, v);
    }
    int klen = 335 - (maxlr - lrb);

    for (int i = tid; i < 16 * 64; i += 128) {
        int r = i >> 6, d = i & 63;
        qs[r][d] = Qb[(((size_t)(qt * 16 + r)) * NB + b) * DMODEL + h * 64 + d] * 0.125f;
    }
    __syncthreads();

    int r = tid >> 3;
    int cg = (tid & 7) * 4;
    int qrow = qt * 16 + r;

    // ---- scores (f32x2 over d) ----
    for (int kc0 = 0; kc0 < KROWS; kc0 += 32) {
        int kcnt = min(32, KROWS - kc0);
        for (int i = tid; i < kcnt * 64; i += 128) {
            int kk = i >> 6, d = i & 63;
            ch[kk][d] = Kb[(((size_t)(kc0 + kk)) * NB + b) * DMODEL + h * 64 + d];
        }
        __syncthreads();
        unsigned long long acc2[4] = {0ull, 0ull, 0ull, 0ull};
#pragma unroll
        for (int d = 0; d < 64; d += 2) {
            unsigned long long qp = *(const unsigned long long*)&qs[r][d];
            FMA2(acc2[0], qp, *(const unsigned long long*)&ch[cg + 0][d]);
            FMA2(acc2[1], qp, *(const unsigned long long*)&ch[cg + 1][d]);
            FMA2(acc2[2], qp, *(const unsigned long long*)&ch[cg + 2][d]);
            FMA2(acc2[3], qp, *(const unsigned long long*)&ch[cg + 3][d]);
        }
#pragma unroll
        for (int j = 0; j < 4; j++) {
            int kc = kc0 + cg + j;
            if (kc < KROWS) {
                float2 t = *(float2*)&acc2[j];
                float av = t.x + t.y;
                sc[r][kc] = (kc < klen && attn_allowed(qrow, kc)) ? av : -1e8f;
            }
        }
        __syncthreads();
    }

    // ---- softmax (8 lanes per row) ----
    {
        int j = tid & 7;
        float m = -3.0e38f;
        for (int c = j; c < KROWS; c += 8) m = fmaxf(m, sc[r][c]);
        for (int o = 4; o; o >>= 1) m = fmaxf(m, __shfl_xor_sync(0xffffffffu, m, o));
        float s = 0.f;
        for (int c = j; c < KROWS; c += 8) {
            float e = __expf(sc[r][c] - m);
            sc[r][c] = e;
            s += e;
        }
        for (int o = 4; o; o >>= 1) s += __shfl_xor_sync(0xffffffffu, s, o);
        if (j == 0) rowsum[r] = s;
    }
    __syncthreads();

    // ---- probs @ V (f32x2 over d pairs) ----
    int dg = (tid & 7) * 8;
    unsigned long long acc[4] = {0ull, 0ull, 0ull, 0ull};
    for (int kc0 = 0; kc0 < KROWS; kc0 += 32) {
        int kcnt = min(32, KROWS - kc0);
        for (int i = tid; i < kcnt * 64; i += 128) {
            int kk = i >> 6, d = i & 63;
            ch[kk][d] = Vb[(((size_t)(kc0 + kk)) * NB + b) * DMODEL + h * 64 + d];
        }
        __syncthreads();
        for (int kk = 0; kk < kcnt; kk++) {
            unsigned long long pd;
            PACK2(pd, sc[r][kc0 + kk]);
            FMA2(acc[0], pd, *(const unsigned long long*)&ch[kk][dg + 0]);
            FMA2(acc[1], pd, *(const unsigned long long*)&ch[kk][dg + 2]);
            FMA2(acc[2], pd, *(const unsigned long long*)&ch[kk][dg + 4]);
            FMA2(acc[3], pd, *(const unsigned long long*)&ch[kk][dg + 6]);
        }
        __syncthreads();
    }
    float inv = 1.0f / rowsum[r];
    float o[8];
#pragma unroll
    for (int u = 0; u < 4; u++) {
        float2 t = *(float2*)&acc[u];
        o[2 * u] = t.x * inv;
        o[2 * u + 1] = t.y * inv;
    }
    float* dst = &Ob[(((size_t)qrow) * NB + b) * DMODEL + h * 64 + dg];
    *(float4*)&dst[0] = make_float4(o[0], o[1], o[2], o[3]);
    *(float4*)&dst[4] = make_float4(o[4], o[5], o[6], o[7]);
}

// ---------------------------------------------------------------------------
// Host driver
// ---------------------------------------------------------------------------
extern "C" void kernel_launch(void* const* d_in, const int* in_sizes, int n_in,
                              void* d_out, int out_size) {
    const float* input   = (const float*)d_in[0];
    const int*   lengths = (const int*)d_in[1];
    const float* w_in    = (const float*)d_in[2];
    const float* ln_in_g = (const float*)d_in[3];
    const float* ln_in_b = (const float*)d_in[4];
    const float* wq      = (const float*)d_in[5];
    const float* bq      = (const float*)d_in[6];
    const float* wk      = (const float*)d_in[7];
    const float* bk      = (const float*)d_in[8];
    const float* wv      = (const float*)d_in[9];
    const float* bv      = (const float*)d_in[10];
    const float* wo      = (const float*)d_in[11];
    const float* bo      = (const float*)d_in[12];
    const float* ff_ln_g = (const float*)d_in[13];
    const float* ff_ln_b = (const float*)d_in[14];
    const float* w1      = (const float*)d_in[15];
    const float* b1      = (const float*)d_in[16];
    const float* w2      = (const float*)d_in[17];
    const float* b2      = (const float*)d_in[18];
    const float* ln_out_g = (const float*)d_in[19];
    const float* ln_out_b = (const float*)d_in[20];
    const float* w_out   = (const float*)d_in[21];
    const float* b_out   = (const float*)d_in[22];
    const float* lng     = (const float*)d_in[23];
    const float* lnb     = (const float*)d_in[24];
    float* out = (float*)d_out;

    float *px, *pstate, *pstate2, *pqin, *pkin, *pq, *pk, *pv, *patt, *pout2;
    float *ph1, *pf1, *pf2, *pyin, *pyt;
    cudaGetSymbolAddress((void**)&px, g_x);
    cudaGetSymbolAddress((void**)&pstate, g_state);
    cudaGetSymbolAddress((void**)&pstate2, g_state2);
    cudaGetSymbolAddress((void**)&pqin, g_qin);
    cudaGetSymbolAddress((void**)&pkin, g_kin);
    cudaGetSymbolAddress((void**)&pq, g_q);
    cudaGetSymbolAddress((void**)&pk, g_k);
    cudaGetSymbolAddress((void**)&pv, g_v);
    cudaGetSymbolAddress((void**)&patt, g_att);
    cudaGetSymbolAddress((void**)&pout2, g_out);
    cudaGetSymbolAddress((void**)&ph1, g_h1);
    cudaGetSymbolAddress((void**)&pf1, g_f1);
    cudaGetSymbolAddress((void**)&pf2, g_f2);
    cudaGetSymbolAddress((void**)&pyin, g_yin);
    cudaGetSymbolAddress((void**)&pyt, g_yt);

    inproj_kernel<<<dim3(1040, 8), 128>>>(input, w_in, px);
    state_init_kernel<<<(STROWS * NB * DMODEL + 255) / 256, 256>>>(px, pstate);
    mems0_kernel<<<(NMEMS * NB * DMODEL + 255) / 256, 256>>>(px, pkin);

    const size_t WSTRIDE = (size_t)DMODEL * DMODEL;
    float* pkin_ln = pkin + (size_t)NMEMS * NB * DMODEL;  // kin rows 15..334

    for (int l = 0; l < 8; l++) {
        // LN1 -> qin rows 0..319 AND kin rows 15..334
        ln4_kernel<512><<<STROWS * NB, 128>>>(pstate, nullptr, nullptr, pqin, pkin_ln,
                                              ln_in_g + l * DMODEL, ln_in_b + l * DMODEL);
        // summary -> qin rows 320..335
        summary_kernel<<<(NSEG * NB * DMODEL + 255) / 256, 256>>>(
            pqin, pqin + (size_t)STROWS * NB * DMODEL);
        // fused Q/K/V projections (504 CTAs)
        sgemm_qkv<<<dim3(8, 21, 3), 256>>>(pqin, pkin,
                                           wq + l * WSTRIDE, wk + l * WSTRIDE, wv + l * WSTRIDE,
                                           bq + l * DMODEL, bk + l * DMODEL, bv + l * DMODEL,
                                           pq, pk, pv);
        attn_kernel<<<dim3(21, 8, 8), 128>>>(pq, pk, pv, lengths, patt);
        sgemm2<<<dim3(8, 21), 256>>>(patt, wo + l * WSTRIDE, bo + l * DMODEL, pout2,
                                     QROWS * NB, DMODEL, DMODEL, 0);
        // new mems -> kin rows 0..14 (safe: K/V proj for this layer already done)
        mems_tanh_kernel<<<(NMEMS * NB * DMODEL + 255) / 256, 256>>>(pout2, pkin);
        // res = out[:320] + state; state2 = res; h1 = LN(res)
        ln4_kernel<512><<<STROWS * NB, 128>>>(pout2, pstate, pstate2, ph1, nullptr,
                                              ff_ln_g + l * DMODEL, ff_ln_b + l * DMODEL);
        sgemm2<<<dim3(32, 20), 256>>>(ph1, w1 + (size_t)l * DMODEL * FFND, b1 + l * FFND,
                                      pf1, STROWS * NB, FFND, DMODEL, 1);
        sgemm2<<<dim3(8, 20), 256>>>(pf1, w2 + (size_t)l * FFND * DMODEL, b2 + l * DMODEL,
                                     pf2, STROWS * NB, DMODEL, FFND, 0);
        ln4_kernel<512><<<STROWS * NB, 128>>>(pf2, pstate2, nullptr, pstate, nullptr,
                                              ln_out_g + l * DMODEL, ln_out_b + l * DMODEL);
    }

    ytrans_kernel<<<(2048 * DMODEL + 255) / 256, 256>>>(pstate, pyin);
    sgemm2<<<dim3(16, 16), 256>>>(pyin, w_out, b_out, pyt, 2048, OUTD, DMODEL, 0);
    ln4_kernel<1024><<<2048, 128>>>(pyt, nullptr, nullptr, out, nullptr, lng, lnb);

    if (out_size >= 8 * 256 * 1024 + 8) {
        lr_kernel<<<1, 8>>>(lengths, out);
    }
}